// round 6
// baseline (speedup 1.0000x reference)
#include <cuda_runtime.h>

typedef unsigned long long ull;

// Problem constants
#define B_  32
#define IC_ 1152
#define OC_ 10
#define ID_ 8
#define OD_ 16
#define N_ITER_ 5
#define EPS_ 1e-20f

#define GI_    8             // ic's per CTA
#define PAIRS_ (GI_ / 2)     // processed 2-at-a-time for ILP
#define NBLK_  (IC_ / GI_)   // 144 CTAs = one wave
#define NTHR_  (OC_ * 32)    // 320 threads: warp = oc, lane = b
#define WPC_   (OC_ * ID_ * OD_)   // 1280 floats of weights per ic

__device__ __forceinline__ float frcp(float a) {
    float r;
    asm("rcp.approx.f32 %0, %1;" : "=f"(r) : "f"(a));
    return r;
}

// Packed fp32x2 ops (sm_103a; only reachable via PTX)
__device__ __forceinline__ ull FMA2(ull a, ull b, ull c) {
    ull d;
    asm("fma.rn.f32x2 %0, %1, %2, %3;" : "=l"(d) : "l"(a), "l"(b), "l"(c));
    return d;
}
__device__ __forceinline__ ull MUL2(ull a, ull b) {
    ull d;
    asm("mul.rn.f32x2 %0, %1, %2;" : "=l"(d) : "l"(a), "l"(b));
    return d;
}
__device__ __forceinline__ ull ADD2(ull a, ull b) {
    ull d;
    asm("add.rn.f32x2 %0, %1, %2;" : "=l"(d) : "l"(a), "l"(b));
    return d;
}
__device__ __forceinline__ ull PACK2(float lo, float hi) {
    ull d;
    asm("mov.b64 %0, {%1, %2};" : "=l"(d) : "f"(lo), "f"(hi));
    return d;
}
__device__ __forceinline__ float LO2(ull v) {
    float lo, hi;
    asm("mov.b64 {%0, %1}, %2;" : "=f"(lo), "=f"(hi) : "l"(v));
    return lo;
}
__device__ __forceinline__ float HI2(ull v) {
    float lo, hi;
    asm("mov.b64 {%0, %1}, %2;" : "=f"(lo), "=f"(hi) : "l"(v));
    return hi;
}
__device__ __forceinline__ float SUM2(ull v) {
    float lo, hi;
    asm("mov.b64 {%0, %1}, %2;" : "=f"(lo), "=f"(hi) : "l"(v));
    return lo + hi;
}

__device__ __forceinline__ unsigned smaddr(const void* p) {
    return (unsigned)__cvta_generic_to_shared(p);
}
#define CP16(dst_u32, src_ptr) \
    asm volatile("cp.async.cg.shared.global [%0], [%1], 16;" \
                 :: "r"(dst_u32), "l"(src_ptr) : "memory")
#define CP_COMMIT()  asm volatile("cp.async.commit_group;" ::: "memory")
#define CP_WAIT0()   asm volatile("cp.async.wait_group 0;" ::: "memory")

__global__ void caps_zero_kernel(float* out, int n) {
    int i = blockIdx.x * blockDim.x + threadIdx.x;
    if (i < n) out[i] = 0.0f;
}

__global__ __launch_bounds__(NTHR_, 1)
void caps_main_kernel(const float* __restrict__ x,
                      const float* __restrict__ w,
                      float* __restrict__ out)
{
    // Double-buffered weights for an ic-PAIR (2x 2560 floats = 20 KB) + alpha
    __shared__ __align__(16) float sw[2][2 * WPC_];
    __shared__ float salpha[2][OC_][32];

    const int tid = threadIdx.x;
    const int c   = tid >> 5;    // warp -> output capsule
    const int b   = tid & 31;    // lane -> batch
    const int i0  = blockIdx.x * GI_;

    ull oacc2[OD_ / 2];
    #pragma unroll
    for (int k = 0; k < OD_ / 2; k++) oacc2[k] = 0ULL;

    // ---- Prologue: async-stage pair 0 weights; load pair 0 x rows ----
    {
        const float4* wg = reinterpret_cast<const float4*>(w + (size_t)i0 * WPC_);
        unsigned s0 = smaddr(&sw[0][0]);
        CP16(s0 + tid * 16, wg + tid);
        CP16(s0 + (tid + NTHR_) * 16, wg + tid + NTHR_);
        CP_COMMIT();
    }
    // x rows for (i0, i0+1): 16 contiguous floats
    float4 xv[4];
    {
        const float4* xp = reinterpret_cast<const float4*>(
            x + ((size_t)b * IC_ + i0) * ID_);
        xv[0] = xp[0]; xv[1] = xp[1]; xv[2] = xp[2]; xv[3] = xp[3];
    }
    CP_WAIT0();
    __syncthreads();

    int pb = 0;
    for (int jj = 0; jj < PAIRS_; jj++) {
        // ---- Stage next pair (global -> smem via cp.async, no regs held) ----
        float4 xn[4];
        if (jj + 1 < PAIRS_) {
            const int inext = i0 + 2 * (jj + 1);
            const float4* wg = reinterpret_cast<const float4*>(
                w + (size_t)inext * WPC_);
            unsigned s1 = smaddr(&sw[pb ^ 1][0]);
            CP16(s1 + tid * 16, wg + tid);
            CP16(s1 + (tid + NTHR_) * 16, wg + tid + NTHR_);
            CP_COMMIT();
            const float4* xp = reinterpret_cast<const float4*>(
                x + ((size_t)b * IC_ + inext) * ID_);
            xn[0] = xp[0]; xn[1] = xp[1]; xn[2] = xp[2]; xn[3] = xp[3];
        }

        // x rows, UNNORMALIZED (scale cancels exactly through the final h and
        // alpha normalizations).
        float xr[2][ID_];
        xr[0][0]=xv[0].x; xr[0][1]=xv[0].y; xr[0][2]=xv[0].z; xr[0][3]=xv[0].w;
        xr[0][4]=xv[1].x; xr[0][5]=xv[1].y; xr[0][6]=xv[1].z; xr[0][7]=xv[1].w;
        xr[1][0]=xv[2].x; xr[1][1]=xv[2].y; xr[1][2]=xv[2].z; xr[1][3]=xv[2].w;
        xr[1][4]=xv[3].x; xr[1][5]=xv[3].y; xr[1][6]=xv[3].z; xr[1][7]=xv[3].w;

        // Per-u capsule weight pointers (uniform across warp: smem broadcast)
        const ulonglong2* wp[2];
        wp[0] = reinterpret_cast<const ulonglong2*>(sw[pb] + c * (ID_ * OD_));
        wp[1] = reinterpret_cast<const ulonglong2*>(sw[pb] + WPC_ + c * (ID_ * OD_));

        // ---- Two independent NNMF chains (u = 0,1), interleaved for ILP ----
        ull cur2[2][OD_ / 2];
        #pragma unroll
        for (int u = 0; u < 2; u++)
            #pragma unroll
            for (int k = 0; k < OD_ / 2; k++)
                cur2[u][k] = 0x3D8000003D800000ULL;  // (1/16, 1/16)

        for (int it = 0; it < N_ITER_; it++) {
            ull acc2[2][OD_ / 2];
            #pragma unroll
            for (int u = 0; u < 2; u++)
                #pragma unroll
                for (int k = 0; k < OD_ / 2; k++) acc2[u][k] = 0ULL;

            #pragma unroll
            for (int d = 0; d < ID_; d++) {
                #pragma unroll
                for (int u = 0; u < 2; u++) {
                    ull wv[OD_ / 2];
                    #pragma unroll
                    for (int q = 0; q < 4; q++) {
                        ulonglong2 v = wp[u][d * 4 + q];
                        wv[2 * q + 0] = v.x;
                        wv[2 * q + 1] = v.y;
                    }
                    // split reduction: two 4-deep chains instead of one 8-deep
                    ull sa = 0ULL, sb = 0ULL;
                    #pragma unroll
                    for (int k = 0; k < 4; k++) {
                        sa = FMA2(cur2[u][k],     wv[k],     sa);
                        sb = FMA2(cur2[u][k + 4], wv[k + 4], sb);
                    }
                    float t = xr[u][d] * frcp(SUM2(ADD2(sa, sb)) + EPS_);
                    ull t2 = PACK2(t, t);
                    #pragma unroll
                    for (int k = 0; k < OD_ / 2; k++)
                        acc2[u][k] = FMA2(wv[k], t2, acc2[u][k]);
                }
            }
            #pragma unroll
            for (int u = 0; u < 2; u++)
                #pragma unroll
                for (int k = 0; k < OD_ / 2; k++)
                    cur2[u][k] = MUL2(cur2[u][k], acc2[u][k]);
        }

        // ---- Epilogue per u: h-normalizer (lazy) + alpha ----
        float hr[2], alpha[2];
        #pragma unroll
        for (int u = 0; u < 2; u++) {
            ull hs = ADD2(ADD2(ADD2(cur2[u][0], cur2[u][1]),
                               ADD2(cur2[u][2], cur2[u][3])),
                          ADD2(ADD2(cur2[u][4], cur2[u][5]),
                               ADD2(cur2[u][6], cur2[u][7])));
            hr[u] = frcp(SUM2(hs) + EPS_);

            float A = 0.0f;
            #pragma unroll
            for (int d = 0; d < ID_; d++) {
                ull sa = 0ULL, sb = 0ULL;
                #pragma unroll
                for (int q = 0; q < 4; q++) {
                    ulonglong2 v = wp[u][d * 4 + q];
                    sa = FMA2(cur2[u][2 * q + 0], v.x, sa);
                    sb = FMA2(cur2[u][2 * q + 1], v.y, sb);
                }
                A = fmaf(xr[u][d], SUM2(ADD2(sa, sb)), A);
            }
            alpha[u] = hr[u] * A;
            salpha[u][c][b] = alpha[u];
        }
        __syncthreads();

        #pragma unroll
        for (int u = 0; u < 2; u++) {
            float asum = 0.0f;
            #pragma unroll
            for (int cc = 0; cc < OC_; cc++) asum += salpha[u][cc][b];
            float sc = hr[u] * alpha[u] * frcp(asum + EPS_);  // h-scale * alpha_n
            ull sc2 = PACK2(sc, sc);
            #pragma unroll
            for (int k = 0; k < OD_ / 2; k++)
                oacc2[k] = FMA2(cur2[u][k], sc2, oacc2[k]);
        }

        // ---- Rotate buffers ----
        if (jj + 1 < PAIRS_) {
            CP_WAIT0();
            __syncthreads();   // staged weights visible; salpha reads done
            xv[0] = xn[0]; xv[1] = xn[1]; xv[2] = xn[2]; xv[3] = xn[3];
            pb ^= 1;
        }
    }

    // ---- Accumulate this CTA's contribution into out[b,c,:] ----
    float* op = out + ((size_t)b * OC_ + c) * OD_;
    #pragma unroll
    for (int k = 0; k < OD_ / 2; k++) {
        atomicAdd(op + 2 * k + 0, LO2(oacc2[k]));
        atomicAdd(op + 2 * k + 1, HI2(oacc2[k]));
    }
}

extern "C" void kernel_launch(void* const* d_in, const int* in_sizes, int n_in,
                              void* d_out, int out_size)
{
    const float* x = (const float*)d_in[0];
    const float* w = (const float*)d_in[1];
    // Defensive: identify tensors by size (x = 294912, w = 1474560).
    if (n_in >= 2 && in_sizes[0] == IC_ * OC_ * ID_ * OD_) {
        const float* t = x; x = w; w = t;
    }
    float* out = (float*)d_out;

    caps_zero_kernel<<<(out_size + 255) / 256, 256>>>(out, out_size);
    caps_main_kernel<<<NBLK_, NTHR_>>>(x, w, out);
}

// round 7
// speedup vs baseline: 1.9496x; 1.9496x over previous
#include <cuda_runtime.h>

typedef unsigned long long ull;

// Problem constants
#define B_  32
#define IC_ 1152
#define OC_ 10
#define ID_ 8
#define OD_ 16
#define N_ITER_ 5
#define EPS_ 1e-20f

#define GI_    8             // ic's per CTA
#define NBLK_  (IC_ / GI_)   // 144 CTAs = one wave
#define NTHR_  640           // 20 warps: warp=(c,bhi), lane=(blo,h); thread owns 8 e's
#define WPC_   (OC_ * ID_ * OD_)   // 1280 floats of weights per ic
#define EH_    (OD_ / 2)           // 8 e's per thread
#define EP_    (EH_ / 2)           // 4 packed f32x2 per thread

__device__ __forceinline__ float frcp(float a) {
    float r;
    asm("rcp.approx.f32 %0, %1;" : "=f"(r) : "f"(a));
    return r;
}

// Packed fp32x2 ops (sm_103a; only reachable via PTX)
__device__ __forceinline__ ull FMA2(ull a, ull b, ull c) {
    ull d;
    asm("fma.rn.f32x2 %0, %1, %2, %3;" : "=l"(d) : "l"(a), "l"(b), "l"(c));
    return d;
}
__device__ __forceinline__ ull MUL2(ull a, ull b) {
    ull d;
    asm("mul.rn.f32x2 %0, %1, %2;" : "=l"(d) : "l"(a), "l"(b));
    return d;
}
__device__ __forceinline__ ull ADD2(ull a, ull b) {
    ull d;
    asm("add.rn.f32x2 %0, %1, %2;" : "=l"(d) : "l"(a), "l"(b));
    return d;
}
__device__ __forceinline__ ull PACK2(float lo, float hi) {
    ull d;
    asm("mov.b64 %0, {%1, %2};" : "=l"(d) : "f"(lo), "f"(hi));
    return d;
}
__device__ __forceinline__ float LO2(ull v) {
    float lo, hi;
    asm("mov.b64 {%0, %1}, %2;" : "=f"(lo), "=f"(hi) : "l"(v));
    return lo;
}
__device__ __forceinline__ float HI2(ull v) {
    float lo, hi;
    asm("mov.b64 {%0, %1}, %2;" : "=f"(lo), "=f"(hi) : "l"(v));
    return hi;
}
__device__ __forceinline__ float SUM2(ull v) {
    float lo, hi;
    asm("mov.b64 {%0, %1}, %2;" : "=f"(lo), "=f"(hi) : "l"(v));
    return lo + hi;
}

__device__ __forceinline__ unsigned smaddr(const void* p) {
    return (unsigned)__cvta_generic_to_shared(p);
}
#define CP8(dst_u32, src_ptr) \
    asm volatile("cp.async.ca.shared.global [%0], [%1], 8;" \
                 :: "r"(dst_u32), "l"(src_ptr) : "memory")
#define CP_COMMIT()  asm volatile("cp.async.commit_group;" ::: "memory")
#define CP_WAIT0()   asm volatile("cp.async.wait_group 0;" ::: "memory")

__global__ void caps_zero_kernel(float* out, int n) {
    int i = blockIdx.x * blockDim.x + threadIdx.x;
    if (i < n) out[i] = 0.0f;
}

__global__ __launch_bounds__(NTHR_, 1)
void caps_main_kernel(const float* __restrict__ x,
                      const float* __restrict__ w,
                      float* __restrict__ out)
{
    // Double-buffered per-ic weights (2 x 1280 floats = 10 KB) + alpha exchange
    __shared__ __align__(16) float sw[2][WPC_];
    __shared__ float salpha[OC_][32];

    const int tid  = threadIdx.x;
    const int wid  = tid >> 5;          // 0..19
    const int lane = tid & 31;
    const int c    = wid >> 1;          // 0..9  output capsule
    const int bhi  = wid & 1;           // which 16 batches
    const int h    = lane & 1;          // e-half: e in [8h, 8h+8)
    const int blo  = lane >> 1;         // 0..15
    const int b    = bhi * 16 + blo;    // batch index
    const int i0   = blockIdx.x * GI_;

    ull oacc2[EP_];
    #pragma unroll
    for (int k = 0; k < EP_; k++) oacc2[k] = 0ULL;

    // ---- Prologue: stage ic0 weights (cp.async), load ic0 x row ----
    {
        const float2* wg = reinterpret_cast<const float2*>(w + (size_t)i0 * WPC_);
        unsigned s0 = smaddr(&sw[0][0]);
        CP8(s0 + tid * 8, wg + tid);    // 640 * float2 = 1280 floats
        CP_COMMIT();
    }
    float4 xa, xb;
    {
        const float4* xp = reinterpret_cast<const float4*>(
            x + ((size_t)b * IC_ + i0) * ID_);
        xa = xp[0]; xb = xp[1];
    }
    CP_WAIT0();
    __syncthreads();

    int pb = 0;
    for (int ii = 0; ii < GI_; ii++) {
        // ---- Stage next ic weights into the other buffer; prefetch next x ----
        float4 xna, xnb;
        if (ii + 1 < GI_) {
            const float2* wg = reinterpret_cast<const float2*>(
                w + (size_t)(i0 + ii + 1) * WPC_);
            unsigned s1 = smaddr(&sw[pb ^ 1][0]);
            CP8(s1 + tid * 8, wg + tid);
            CP_COMMIT();
            const float4* xp = reinterpret_cast<const float4*>(
                x + ((size_t)b * IC_ + (i0 + ii + 1)) * ID_);
            xna = xp[0]; xnb = xp[1];
        }

        // x row, UNNORMALIZED (scale cancels exactly through the final h and
        // alpha normalizations).
        float xr[ID_];
        xr[0] = xa.x; xr[1] = xa.y; xr[2] = xa.z; xr[3] = xa.w;
        xr[4] = xb.x; xr[5] = xb.y; xr[6] = xb.z; xr[7] = xb.w;

        // This thread's weight slice: w[i, c, d, 8h..8h+8). Row d = 2 x 16B.
        // Per warp only 2 distinct addresses per load -> smem broadcast.
        const ulonglong2* wq = reinterpret_cast<const ulonglong2*>(
            sw[pb] + c * (ID_ * OD_) + h * EH_);

        // ---- NNMF (multiplicative update, renorm deferred), e-split x2 ----
        //   s_d     = sum_e cur[e]*w[d,e]   (half-dot + shfl with partner lane)
        //   cur[e] *= sum_d x[d]*w[d,e] / (s_d + EPS)
        ull cur2[EP_];
        #pragma unroll
        for (int k = 0; k < EP_; k++)
            cur2[k] = 0x3D8000003D800000ULL;  // (1/16, 1/16)

        for (int it = 0; it < N_ITER_; it++) {
            ull acc2[EP_];
            #pragma unroll
            for (int k = 0; k < EP_; k++) acc2[k] = 0ULL;

            #pragma unroll
            for (int d = 0; d < ID_; d++) {
                ulonglong2 v0 = wq[d * 4 + 0];   // floats [8h, 8h+4)
                ulonglong2 v1 = wq[d * 4 + 1];   // floats [8h+4, 8h+8)
                ull sa = FMA2(cur2[0], v0.x, 0ULL);
                ull sb = FMA2(cur2[1], v0.y, 0ULL);
                sa = FMA2(cur2[2], v1.x, sa);
                sb = FMA2(cur2[3], v1.y, sb);
                float sp = SUM2(ADD2(sa, sb));                    // my half
                float s  = sp + __shfl_xor_sync(0xffffffffu, sp, 1);
                float t  = xr[d] * frcp(s + EPS_);
                ull t2 = PACK2(t, t);
                acc2[0] = FMA2(v0.x, t2, acc2[0]);
                acc2[1] = FMA2(v0.y, t2, acc2[1]);
                acc2[2] = FMA2(v1.x, t2, acc2[2]);
                acc2[3] = FMA2(v1.y, t2, acc2[3]);
            }
            #pragma unroll
            for (int k = 0; k < EP_; k++) cur2[k] = MUL2(cur2[k], acc2[k]);
        }

        // ---- h normalization factor (lazy, full sum via shfl) ----
        float hp = SUM2(ADD2(ADD2(cur2[0], cur2[1]), ADD2(cur2[2], cur2[3])));
        float hs = hp + __shfl_xor_sync(0xffffffffu, hp, 1);
        float hr = frcp(hs + EPS_);

        // ---- alpha = hr * sum_d x[d] * (cur . w[d,:]) ----
        float A = 0.0f;
        #pragma unroll
        for (int d = 0; d < ID_; d++) {
            ulonglong2 v0 = wq[d * 4 + 0];
            ulonglong2 v1 = wq[d * 4 + 1];
            ull sa = FMA2(cur2[0], v0.x, 0ULL);
            ull sb = FMA2(cur2[1], v0.y, 0ULL);
            sa = FMA2(cur2[2], v1.x, sa);
            sb = FMA2(cur2[3], v1.y, sb);
            A = fmaf(xr[d], SUM2(ADD2(sa, sb)), A);
        }
        A = A + __shfl_xor_sync(0xffffffffu, A, 1);   // full-e dot
        float alpha = hr * A;

        salpha[c][b] = alpha;   // both halves write the identical value
        __syncthreads();

        float asum = 0.0f;
        #pragma unroll
        for (int cc = 0; cc < OC_; cc++) asum += salpha[cc][b];
        float sc = hr * alpha * frcp(asum + EPS_);    // h-scale * alpha_n
        ull sc2 = PACK2(sc, sc);
        #pragma unroll
        for (int k = 0; k < EP_; k++) oacc2[k] = FMA2(cur2[k], sc2, oacc2[k]);

        // ---- Rotate buffers ----
        if (ii + 1 < GI_) {
            CP_WAIT0();
            __syncthreads();   // staged weights visible; salpha reads done
            xa = xna; xb = xnb;
            pb ^= 1;
        }
    }

    // ---- Accumulate this CTA's contribution into out[b, c, 8h..8h+8) ----
    float* op = out + ((size_t)b * OC_ + c) * OD_ + h * EH_;
    #pragma unroll
    for (int k = 0; k < EP_; k++) {
        atomicAdd(op + 2 * k + 0, LO2(oacc2[k]));
        atomicAdd(op + 2 * k + 1, HI2(oacc2[k]));
    }
}

extern "C" void kernel_launch(void* const* d_in, const int* in_sizes, int n_in,
                              void* d_out, int out_size)
{
    const float* x = (const float*)d_in[0];
    const float* w = (const float*)d_in[1];
    // Defensive: identify tensors by size (x = 294912, w = 1474560).
    if (n_in >= 2 && in_sizes[0] == IC_ * OC_ * ID_ * OD_) {
        const float* t = x; x = w; w = t;
    }
    float* out = (float*)d_out;

    caps_zero_kernel<<<(out_size + 255) / 256, 256>>>(out, out_size);
    caps_main_kernel<<<NBLK_, NTHR_>>>(x, w, out);
}